// round 4
// baseline (speedup 1.0000x reference)
#include <cuda_runtime.h>
#include <cuda_bf16.h>
#include <cstdint>

#define NB 8
#define SQ 2048
#define SK 2048
#define DQK 128
#define DV 128

#define SW 24     // bf16 stride, k-major 16-col tiles (48B rows, odd 16B units)
#define AW 72     // bf16 stride for p tile rows (144B, 9x16B odd)
#define BW 136    // bf16 stride for V tile rows (272B, 17x16B odd)

// bf16 hi/lo scratch
__device__ uint16_t g_qwh[NB * SQ * DQK], g_qwl[NB * SQ * DQK];
__device__ uint16_t g_kh[NB * SK * DQK],  g_kl[NB * SK * DQK];
__device__ uint16_t g_vh[NB * SK * DV],   g_vl[NB * SK * DV];
__device__ float    g_inv[NB * SQ];

// ---------------------------------------------------------------------------
struct HL { uint32_t h, l; };

__device__ __forceinline__ HL split2(float x, float y) {
    __nv_bfloat162 hh = __floats2bfloat162_rn(x, y);
    float hx = __bfloat162float(__low2bfloat16(hh));
    float hy = __bfloat162float(__high2bfloat16(hh));
    __nv_bfloat162 ll = __floats2bfloat162_rn(x - hx, y - hy);
    HL r;
    r.h = *reinterpret_cast<uint32_t*>(&hh);
    r.l = *reinterpret_cast<uint32_t*>(&ll);
    return r;
}

__device__ __forceinline__ void mma_bf16(float* c, const uint32_t* a,
                                         uint32_t b0, uint32_t b1) {
    asm volatile(
        "mma.sync.aligned.m16n8k16.row.col.f32.bf16.bf16.f32 "
        "{%0,%1,%2,%3}, {%4,%5,%6,%7}, {%8,%9}, {%0,%1,%2,%3};"
        : "+f"(c[0]), "+f"(c[1]), "+f"(c[2]), "+f"(c[3])
        : "r"(a[0]), "r"(a[1]), "r"(a[2]), "r"(a[3]), "r"(b0), "r"(b1));
}

__device__ __forceinline__ void ldsm_x4(uint32_t& r0, uint32_t& r1, uint32_t& r2,
                                        uint32_t& r3, uint32_t addr) {
    asm volatile("ldmatrix.sync.aligned.m8n8.x4.shared.b16 {%0,%1,%2,%3}, [%4];"
                 : "=r"(r0), "=r"(r1), "=r"(r2), "=r"(r3) : "r"(addr));
}

__device__ __forceinline__ void ldsm_x4_t(uint32_t& r0, uint32_t& r1, uint32_t& r2,
                                          uint32_t& r3, uint32_t addr) {
    asm volatile("ldmatrix.sync.aligned.m8n8.x4.trans.shared.b16 {%0,%1,%2,%3}, [%4];"
                 : "=r"(r0), "=r"(r1), "=r"(r2), "=r"(r3) : "r"(addr));
}

// ---------------------------------------------------------------------------
// Prep: convert K and V fp32 -> bf16 hi/lo. 2M elems each, 8 per thread.
// ---------------------------------------------------------------------------
__global__ void prep_kv(const float* __restrict__ K, const float* __restrict__ V) {
    size_t i = ((size_t)blockIdx.x * 256 + threadIdx.x) * 8;
    float4 a0 = *(const float4*)&K[i];
    float4 a1 = *(const float4*)&K[i + 4];
    HL k0 = split2(a0.x, a0.y), k1 = split2(a0.z, a0.w);
    HL k2 = split2(a1.x, a1.y), k3 = split2(a1.z, a1.w);
    uint4 hv = {k0.h, k1.h, k2.h, k3.h};
    uint4 lv = {k0.l, k1.l, k2.l, k3.l};
    *(uint4*)&g_kh[i] = hv;
    *(uint4*)&g_kl[i] = lv;

    float4 b0 = *(const float4*)&V[i];
    float4 b1 = *(const float4*)&V[i + 4];
    HL v0 = split2(b0.x, b0.y), v1 = split2(b0.z, b0.w);
    HL v2 = split2(b1.x, b1.y), v3 = split2(b1.z, b1.w);
    uint4 hw = {v0.h, v1.h, v2.h, v3.h};
    uint4 lw = {v0.l, v1.l, v2.l, v3.l};
    *(uint4*)&g_vh[i] = hw;
    *(uint4*)&g_vl[i] = lw;
}

// ---------------------------------------------------------------------------
// Kernel 1: QW = Q @ W  (fp32 FFMA), writes bf16 hi/lo.
// ---------------------------------------------------------------------------
__global__ void qw_kernel(const float* __restrict__ Q, const float* __restrict__ W) {
    __shared__ float sAt[32][65];
    __shared__ float sB[32][128];

    const int tid = threadIdx.x;
    const int tx = tid & 15;
    const int ty = tid >> 4;
    const int m0 = blockIdx.x * 64;

    float acc[4][8];
#pragma unroll
    for (int i = 0; i < 4; i++)
#pragma unroll
        for (int j = 0; j < 8; j++) acc[i][j] = 0.f;

    for (int kk = 0; kk < DQK; kk += 32) {
#pragma unroll
        for (int r = 0; r < 8; r++) {
            int idx = tid + r * 256;
            int m = idx >> 5, k = idx & 31;
            sAt[k][m] = Q[(size_t)(m0 + m) * DQK + kk + k];
        }
#pragma unroll
        for (int r = 0; r < 16; r++) {
            int idx = tid + r * 256;
            int k = idx >> 7, n = idx & 127;
            sB[k][n] = W[(size_t)(kk + k) * DQK + n];
        }
        __syncthreads();

#pragma unroll
        for (int k = 0; k < 32; k++) {
            float a[4];
#pragma unroll
            for (int i = 0; i < 4; i++) a[i] = sAt[k][ty * 4 + i];
            float4 b0 = *(const float4*)&sB[k][tx * 8];
            float4 b1 = *(const float4*)&sB[k][tx * 8 + 4];
            float b[8] = {b0.x, b0.y, b0.z, b0.w, b1.x, b1.y, b1.z, b1.w};
#pragma unroll
            for (int i = 0; i < 4; i++)
#pragma unroll
                for (int j = 0; j < 8; j++) acc[i][j] = fmaf(a[i], b[j], acc[i][j]);
        }
        __syncthreads();
    }

#pragma unroll
    for (int i = 0; i < 4; i++) {
        size_t row = (size_t)(m0 + ty * 4 + i) * DQK + tx * 8;
        HL p0 = split2(acc[i][0], acc[i][1]), p1 = split2(acc[i][2], acc[i][3]);
        HL p2 = split2(acc[i][4], acc[i][5]), p3 = split2(acc[i][6], acc[i][7]);
        uint4 hv = {p0.h, p1.h, p2.h, p3.h};
        uint4 lv = {p0.l, p1.l, p2.l, p3.l};
        *(uint4*)&g_qwh[row] = hv;
        *(uint4*)&g_qwl[row] = lv;
    }
}

// ---------------------------------------------------------------------------
// Kernel 2: S = QW @ K^T via bf16x3 mma.sync, precomputed bf16 operands.
// grid (SK/128, SQ/128, NB), block 256 = 8 warps (2x4). Tile 128x128, k=16.
// ---------------------------------------------------------------------------
__global__ void __launch_bounds__(256, 2)
score_kernel(float* __restrict__ Wout) {
    __shared__ __align__(16) uint16_t sA[2][2][128 * SW];
    __shared__ __align__(16) uint16_t sB[2][2][128 * SW];

    const int tid = threadIdx.x;
    const int warp = tid >> 5, lane = tid & 31;
    const int warpM = warp >> 2, warpN = warp & 3;
    const int gid = lane >> 2, tig = lane & 3;

    const int s0 = blockIdx.x * 128;
    const int q0 = blockIdx.y * 128;
    const int b = blockIdx.z;

    const size_t abase = ((size_t)b * SQ + q0) * DQK;
    const size_t bbase = ((size_t)b * SK + s0) * DQK;

    const int lrow = tid >> 1;
    const int lkb = (tid & 1) * 8;

    const int g = lane >> 3, lr = lane & 7;
    const uint32_t aoff = (uint32_t)(((((g & 1) * 8 + lr) * SW) + (g >> 1) * 8) * 2);
    const uint32_t boff = (uint32_t)((((warpN * 32 + (g >> 1) * 8 + lr) * SW) + (g & 1) * 8) * 2);

    const uint32_t sAbase = (uint32_t)__cvta_generic_to_shared(&sA[0][0][0]);
    const uint32_t sBbase = (uint32_t)__cvta_generic_to_shared(&sB[0][0][0]);
    const uint32_t HLSTRIDE = 128 * SW * 2;

    float c[4][4][4];
#pragma unroll
    for (int i = 0; i < 4; i++)
#pragma unroll
        for (int j = 0; j < 4; j++)
#pragma unroll
            for (int r = 0; r < 4; r++) c[i][j][r] = 0.f;

    // prologue: chunk 0 -> buf 0
    uint4 ha = *(const uint4*)&g_qwh[abase + (size_t)lrow * DQK + lkb];
    uint4 la = *(const uint4*)&g_qwl[abase + (size_t)lrow * DQK + lkb];
    uint4 hb = *(const uint4*)&g_kh[bbase + (size_t)lrow * DQK + lkb];
    uint4 lb = *(const uint4*)&g_kl[bbase + (size_t)lrow * DQK + lkb];
    *(uint4*)&sA[0][0][lrow * SW + lkb] = ha;
    *(uint4*)&sA[0][1][lrow * SW + lkb] = la;
    *(uint4*)&sB[0][0][lrow * SW + lkb] = hb;
    *(uint4*)&sB[0][1][lrow * SW + lkb] = lb;
    __syncthreads();

    int buf = 0;
#pragma unroll 1
    for (int chunk = 0; chunk < 8; chunk++) {
        if (chunk < 7) {
            int kk = (chunk + 1) * 16;
            ha = *(const uint4*)&g_qwh[abase + (size_t)lrow * DQK + kk + lkb];
            la = *(const uint4*)&g_qwl[abase + (size_t)lrow * DQK + kk + lkb];
            hb = *(const uint4*)&g_kh[bbase + (size_t)lrow * DQK + kk + lkb];
            lb = *(const uint4*)&g_kl[bbase + (size_t)lrow * DQK + kk + lkb];
        }

        {
            const uint32_t bhi = sBbase + (uint32_t)buf * 2 * HLSTRIDE + boff;
            const uint32_t blo = bhi + HLSTRIDE;
            uint32_t bh[4][2], bl[4][2];
#pragma unroll
            for (int jj = 0; jj < 2; jj++) {
                ldsm_x4(bh[2 * jj][0], bh[2 * jj][1], bh[2 * jj + 1][0], bh[2 * jj + 1][1],
                        bhi + (uint32_t)(jj * 16 * SW * 2));
                ldsm_x4(bl[2 * jj][0], bl[2 * jj][1], bl[2 * jj + 1][0], bl[2 * jj + 1][1],
                        blo + (uint32_t)(jj * 16 * SW * 2));
            }
            const uint32_t ahi = sAbase + (uint32_t)buf * 2 * HLSTRIDE + aoff;
            const uint32_t alo = ahi + HLSTRIDE;
#pragma unroll
            for (int i = 0; i < 4; i++) {
                uint32_t arow = (uint32_t)((warpM * 64 + i * 16) * SW * 2);
                uint32_t ah[4], al[4];
                ldsm_x4(ah[0], ah[1], ah[2], ah[3], ahi + arow);
                ldsm_x4(al[0], al[1], al[2], al[3], alo + arow);
#pragma unroll
                for (int j = 0; j < 4; j++) {
                    mma_bf16(c[i][j], ah, bh[j][0], bh[j][1]);
                    mma_bf16(c[i][j], ah, bl[j][0], bl[j][1]);
                    mma_bf16(c[i][j], al, bh[j][0], bh[j][1]);
                }
            }
        }

        if (chunk < 7) {
            int nb = buf ^ 1;
            *(uint4*)&sA[nb][0][lrow * SW + lkb] = ha;
            *(uint4*)&sA[nb][1][lrow * SW + lkb] = la;
            *(uint4*)&sB[nb][0][lrow * SW + lkb] = hb;
            *(uint4*)&sB[nb][1][lrow * SW + lkb] = lb;
            __syncthreads();
        }
        buf ^= 1;
    }

#pragma unroll
    for (int i = 0; i < 4; i++) {
        int r1 = q0 + warpM * 64 + i * 16 + gid;
#pragma unroll
        for (int j = 0; j < 4; j++) {
            int col = s0 + warpN * 32 + j * 8 + tig * 2;
            float2 v0 = {c[i][j][0], c[i][j][1]};
            float2 v1 = {c[i][j][2], c[i][j][3]};
            *(float2*)&Wout[((size_t)b * SQ + r1) * SK + col] = v0;
            *(float2*)&Wout[((size_t)b * SQ + r1 + 8) * SK + col] = v1;
        }
    }
}

// ---------------------------------------------------------------------------
// Kernel 3 (pass A): row sums of exp(score). One block per row.
// No max subtraction: |score| < ~70 so exp stays in fp32 range.
// ---------------------------------------------------------------------------
__global__ void rowsum_kernel(const float* __restrict__ w) {
    const float4* p = (const float4*)(w + (size_t)blockIdx.x * SK);
    const int t = threadIdx.x;
    __shared__ float red[8];

    float4 v0 = p[t];
    float4 v1 = p[t + 256];
    float sum = __expf(v0.x) + __expf(v0.y) + __expf(v0.z) + __expf(v0.w) +
                __expf(v1.x) + __expf(v1.y) + __expf(v1.z) + __expf(v1.w);
#pragma unroll
    for (int o = 16; o > 0; o >>= 1) sum += __shfl_xor_sync(~0u, sum, o);
    if ((t & 31) == 0) red[t >> 5] = sum;
    __syncthreads();
    if (t == 0) {
        float tot = 0.f;
#pragma unroll
        for (int i = 0; i < 8; i++) tot += red[i];
        g_inv[blockIdx.x] = 1.f / tot;
    }
}

// ---------------------------------------------------------------------------
// Kernel 4 (pass B): fused normalize + PV.
// grid (SQ/64, NB), block 256 = 8 warps (2 Mwarps x 4 Nwarps).
// Per s-chunk 64: read scores, p = exp(s)*inv, write p to weight output,
// split to bf16 hi/lo in smem; V chunk bf16 hi/lo from prep; MMA accumulate.
// ---------------------------------------------------------------------------
__global__ void __launch_bounds__(256, 2)
pv_fused(float* __restrict__ Wout, float* __restrict__ out) {
    __shared__ __align__(16) uint16_t sAh[64 * AW], sAl[64 * AW];
    __shared__ __align__(16) uint16_t sBh[64 * BW], sBl[64 * BW];

    const int tid = threadIdx.x;
    const int warp = tid >> 5, lane = tid & 31;
    const int warpM = warp >> 2, warpN = warp & 3;
    const int gid = lane >> 2, tig = lane & 3;

    const int q0 = blockIdx.x * 64;
    const int b = blockIdx.y;

    float* Sb = Wout + ((size_t)b * SQ + q0) * SK;

    // score/p indices: thread -> row tid>>2, 16 cols at (tid&3)*16
    const int srow = tid >> 2;
    const int scol = (tid & 3) * 16;
    const float inv = g_inv[(size_t)b * SQ + q0 + srow];

    // V indices: row tid>>2, 32 cols at (tid&3)*32
    const int vrow = tid >> 2;
    const int vcol = (tid & 3) * 32;
    const size_t vbase = ((size_t)b * SK) * DV;

    const int g = lane >> 3, lr = lane & 7;
    const uint32_t aoff = (uint32_t)(((((g & 1) * 8 + lr) * AW) + (g >> 1) * 8) * 2);
    const uint32_t btoff = (uint32_t)((((g & 1) * 8 + lr) * BW + (warpN * 32 + (g >> 1) * 8)) * 2);

    const uint32_t sAhB = (uint32_t)__cvta_generic_to_shared(sAh);
    const uint32_t sAlB = (uint32_t)__cvta_generic_to_shared(sAl);
    const uint32_t sBhB = (uint32_t)__cvta_generic_to_shared(sBh);
    const uint32_t sBlB = (uint32_t)__cvta_generic_to_shared(sBl);

    float c[2][4][4];
#pragma unroll
    for (int i = 0; i < 2; i++)
#pragma unroll
        for (int j = 0; j < 4; j++)
#pragma unroll
            for (int r = 0; r < 4; r++) c[i][j][r] = 0.f;

#pragma unroll 1
    for (int ss = 0; ss < SK; ss += 64) {
        // --- scores -> p -> (gmem writeback, smem bf16 hi/lo)
        float* rp = Sb + (size_t)srow * SK + ss + scol;
        float4 s0 = *(float4*)&rp[0];
        float4 s1 = *(float4*)&rp[4];
        float4 s2 = *(float4*)&rp[8];
        float4 s3 = *(float4*)&rp[12];
        s0.x = __expf(s0.x) * inv; s0.y = __expf(s0.y) * inv;
        s0.z = __expf(s0.z) * inv; s0.w = __expf(s0.w) * inv;
        s1.x = __expf(s1.x) * inv; s1.y = __expf(s1.y) * inv;
        s1.z = __expf(s1.z) * inv; s1.w = __expf(s1.w) * inv;
        s2.x = __expf(s2.x) * inv; s2.y = __expf(s2.y) * inv;
        s2.z = __expf(s2.z) * inv; s2.w = __expf(s2.w) * inv;
        s3.x = __expf(s3.x) * inv; s3.y = __expf(s3.y) * inv;
        s3.z = __expf(s3.z) * inv; s3.w = __expf(s3.w) * inv;
        *(float4*)&rp[0] = s0;
        *(float4*)&rp[4] = s1;
        *(float4*)&rp[8] = s2;
        *(float4*)&rp[12] = s3;
        {
            HL p0 = split2(s0.x, s0.y), p1 = split2(s0.z, s0.w);
            HL p2 = split2(s1.x, s1.y), p3 = split2(s1.z, s1.w);
            HL p4 = split2(s2.x, s2.y), p5 = split2(s2.z, s2.w);
            HL p6 = split2(s3.x, s3.y), p7 = split2(s3.z, s3.w);
            uint4 h0 = {p0.h, p1.h, p2.h, p3.h};
            uint4 h1 = {p4.h, p5.h, p6.h, p7.h};
            uint4 l0 = {p0.l, p1.l, p2.l, p3.l};
            uint4 l1 = {p4.l, p5.l, p6.l, p7.l};
            *(uint4*)&sAh[srow * AW + scol] = h0;
            *(uint4*)&sAh[srow * AW + scol + 8] = h1;
            *(uint4*)&sAl[srow * AW + scol] = l0;
            *(uint4*)&sAl[srow * AW + scol + 8] = l1;
        }
        // --- V chunk bf16 hi/lo
        {
            size_t vi = vbase + (size_t)(ss + vrow) * DV + vcol;
            uint4 w0 = *(const uint4*)&g_vh[vi];
            uint4 w1 = *(const uint4*)&g_vh[vi + 8];
            uint4 w2 = *(const uint4*)&g_vh[vi + 16];
            uint4 w3 = *(const uint4*)&g_vh[vi + 24];
            *(uint4*)&sBh[vrow * BW + vcol] = w0;
            *(uint4*)&sBh[vrow * BW + vcol + 8] = w1;
            *(uint4*)&sBh[vrow * BW + vcol + 16] = w2;
            *(uint4*)&sBh[vrow * BW + vcol + 24] = w3;
            uint4 x0 = *(const uint4*)&g_vl[vi];
            uint4 x1 = *(const uint4*)&g_vl[vi + 8];
            uint4 x2 = *(const uint4*)&g_vl[vi + 16];
            uint4 x3 = *(const uint4*)&g_vl[vi + 24];
            *(uint4*)&sBl[vrow * BW + vcol] = x0;
            *(uint4*)&sBl[vrow * BW + vcol + 8] = x1;
            *(uint4*)&sBl[vrow * BW + vcol + 16] = x2;
            *(uint4*)&sBl[vrow * BW + vcol + 24] = x3;
        }
        __syncthreads();

        // --- MMA: 4 k16 steps over the 64-s chunk
#pragma unroll
        for (int ks = 0; ks < 4; ks++) {
            const uint32_t k0 = ks * 16;
            uint32_t bh[4][2], bl[4][2];
#pragma unroll
            for (int jj = 0; jj < 2; jj++) {
                uint32_t badd = k0 * BW * 2 + btoff + (uint32_t)(jj * 32);
                ldsm_x4_t(bh[2 * jj][0], bh[2 * jj][1], bh[2 * jj + 1][0], bh[2 * jj + 1][1],
                          sBhB + badd);
                ldsm_x4_t(bl[2 * jj][0], bl[2 * jj][1], bl[2 * jj + 1][0], bl[2 * jj + 1][1],
                          sBlB + badd);
            }
#pragma unroll
            for (int i = 0; i < 2; i++) {
                uint32_t ar = (uint32_t)((warpM * 32 + i * 16) * AW * 2) + k0 * 2 + aoff;
                uint32_t ah[4], al[4];
                ldsm_x4(ah[0], ah[1], ah[2], ah[3], sAhB + ar);
                ldsm_x4(al[0], al[1], al[2], al[3], sAlB + ar);
#pragma unroll
                for (int j = 0; j < 4; j++) {
                    mma_bf16(c[i][j], ah, bh[j][0], bh[j][1]);
                    mma_bf16(c[i][j], ah, bl[j][0], bl[j][1]);
                    mma_bf16(c[i][j], al, bh[j][0], bh[j][1]);
                }
            }
        }
        __syncthreads();
    }

    // epilogue
#pragma unroll
    for (int i = 0; i < 2; i++) {
        int r1 = q0 + warpM * 32 + i * 16 + gid;
#pragma unroll
        for (int j = 0; j < 4; j++) {
            int col = warpN * 32 + j * 8 + tig * 2;
            float2 v0 = {c[i][j][0], c[i][j][1]};
            float2 v1 = {c[i][j][2], c[i][j][3]};
            *(float2*)&out[((size_t)b * SQ + r1) * DV + col] = v0;
            *(float2*)&out[((size_t)b * SQ + r1 + 8) * DV + col] = v1;
        }
    }
}

// ---------------------------------------------------------------------------
extern "C" void kernel_launch(void* const* d_in, const int* in_sizes, int n_in,
                              void* d_out, int out_size) {
    const float* Q = (const float*)d_in[0];   // [B,SQ,DQ]
    const float* K = (const float*)d_in[1];   // [B,SK,DK]
    const float* V = (const float*)d_in[2];   // [B,SK,DV]
    const float* W = (const float*)d_in[3];   // [DQ,DK]

    float* out  = (float*)d_out;                          // [B,SQ,DV]
    float* wout = (float*)d_out + (size_t)NB * SQ * DV;   // [B,SQ,SK]

    prep_kv<<<NB * SK * DQK / 2048, 256>>>(K, V);
    qw_kernel<<<NB * SQ / 64, 256>>>(Q, W);

    dim3 sg(SK / 128, SQ / 128, NB);
    score_kernel<<<sg, 256>>>(wout);

    rowsum_kernel<<<NB * SQ, 256>>>(wout);

    dim3 pg(SQ / 64, NB);
    pv_fused<<<pg, 256>>>(wout, out);
}